// round 1
// baseline (speedup 1.0000x reference)
#include <cuda_runtime.h>

// UnarySqrt recurrence, unipolar, jk_trace=True.
// Per column: out = (1-trace)*x + trace ; trace' = out*(1-trace).
// On {0,1} values this simplifies exactly to:
//   trace_next = x * (1 - trace)   (since trace*(1-trace) == 0)
//   out        = trace_next + trace (disjoint add, exact)
//
// T = 64 sequential steps, N = 1,048,576 independent channels.
// One thread owns 4 channels (float4). Pure HBM streaming: 256MB in, 256MB out.

#define T_STEPS 64

__global__ __launch_bounds__(256)
void unary_sqrt_kernel(const float4* __restrict__ bits,
                       const float4* __restrict__ trace0,
                       float4* __restrict__ out,
                       int nvec)
{
    int i = blockIdx.x * blockDim.x + threadIdx.x;
    if (i >= nvec) return;

    float4 tr = trace0[i];

    #pragma unroll 8
    for (int t = 0; t < T_STEPS; ++t) {
        float4 x = __ldg(&bits[(size_t)t * nvec + i]);
        float4 o;

        float n0 = x.x * (1.0f - tr.x);
        float n1 = x.y * (1.0f - tr.y);
        float n2 = x.z * (1.0f - tr.z);
        float n3 = x.w * (1.0f - tr.w);

        o.x = n0 + tr.x;
        o.y = n1 + tr.y;
        o.z = n2 + tr.z;
        o.w = n3 + tr.w;

        tr.x = n0; tr.y = n1; tr.z = n2; tr.w = n3;

        out[(size_t)t * nvec + i] = o;
    }
}

extern "C" void kernel_launch(void* const* d_in, const int* in_sizes, int n_in,
                              void* d_out, int out_size)
{
    // metadata order: input [T, N] float32, trace0 [N] float32
    const float4* bits   = (const float4*)d_in[0];
    const float4* trace0 = (const float4*)d_in[1];
    float4*       out    = (float4*)d_out;

    int N    = in_sizes[1];      // trace0 element count = N
    int nvec = N / 4;            // N = 1048576 -> 262144 vectors

    int threads = 256;
    int blocks  = (nvec + threads - 1) / threads;
    unary_sqrt_kernel<<<blocks, threads>>>(bits, trace0, out, nvec);
}

// round 2
// speedup vs baseline: 1.0165x; 1.0165x over previous
#include <cuda_runtime.h>

// UnarySqrt recurrence, unipolar, jk_trace=True.
//   trace_next = x * (1 - trace)  ;  out = trace_next + trace   (exact on {0,1})
// T=64 sequential steps, N=1,048,576 channels. Pure HBM streaming (256MB+256MB).
//
// R2: two independent float4 column-groups per thread (i and i+half) to double
// in-flight loads per thread (MLP), plus streaming cache hints (touch-once data).

#define T_STEPS 64

__global__ __launch_bounds__(256)
void unary_sqrt_kernel(const float4* __restrict__ bits,
                       const float4* __restrict__ trace0,
                       float4* __restrict__ out,
                       int nvec, int half)
{
    int i = blockIdx.x * blockDim.x + threadIdx.x;
    if (i >= half) return;
    int j = i + half;

    float4 ta = __ldcs(&trace0[i]);
    float4 tb = __ldcs(&trace0[j]);

    #pragma unroll 8
    for (int t = 0; t < T_STEPS; ++t) {
        const size_t base = (size_t)t * nvec;
        float4 xa = __ldcs(&bits[base + i]);
        float4 xb = __ldcs(&bits[base + j]);

        float a0 = xa.x * (1.0f - ta.x);
        float a1 = xa.y * (1.0f - ta.y);
        float a2 = xa.z * (1.0f - ta.z);
        float a3 = xa.w * (1.0f - ta.w);
        float b0 = xb.x * (1.0f - tb.x);
        float b1 = xb.y * (1.0f - tb.y);
        float b2 = xb.z * (1.0f - tb.z);
        float b3 = xb.w * (1.0f - tb.w);

        float4 oa = make_float4(a0 + ta.x, a1 + ta.y, a2 + ta.z, a3 + ta.w);
        float4 ob = make_float4(b0 + tb.x, b1 + tb.y, b2 + tb.z, b3 + tb.w);

        ta = make_float4(a0, a1, a2, a3);
        tb = make_float4(b0, b1, b2, b3);

        __stcs(&out[base + i], oa);
        __stcs(&out[base + j], ob);
    }
}

extern "C" void kernel_launch(void* const* d_in, const int* in_sizes, int n_in,
                              void* d_out, int out_size)
{
    // metadata order: input [T, N] float32, trace0 [N] float32
    const float4* bits   = (const float4*)d_in[0];
    const float4* trace0 = (const float4*)d_in[1];
    float4*       out    = (float4*)d_out;

    int N    = in_sizes[1];   // 1048576
    int nvec = N / 4;         // 262144
    int half = nvec / 2;      // 131072

    int threads = 256;
    int blocks  = (half + threads - 1) / threads;  // 512
    unary_sqrt_kernel<<<blocks, threads>>>(bits, trace0, out, nvec, half);
}